// round 1
// baseline (speedup 1.0000x reference)
#include <cuda_runtime.h>
#include <math.h>

// Problem shape (fixed by the dataset)
#define NMAX 100000
#define EMAX 1600000
#define EPS 1e-5f

// ---- device scratch (no allocations allowed in kernel_launch) ----
__device__ int   g_deg [NMAX];
__device__ float g_dinv[NMAX];
__device__ float g_norm[EMAX];
__device__ float g_h   [(size_t)NMAX * 64];   // GEMM output of current layer
__device__ float g_agg [(size_t)NMAX * 64];   // aggregation output

// ---------------------------------------------------------------
// Normalization setup: deg = 1 + outdegree(row); dinv = rsqrt(deg);
// norm[e] = dinv[row]*dinv[col]
// ---------------------------------------------------------------
__global__ void k_zero_deg(int N) {
    int i = blockIdx.x * blockDim.x + threadIdx.x;
    if (i < N) g_deg[i] = 0;
}

__global__ void k_count(const int* __restrict__ row, int E) {
    int e = blockIdx.x * blockDim.x + threadIdx.x;
    if (e < E) atomicAdd(&g_deg[row[e]], 1);
}

__global__ void k_dinv(int N) {
    int i = blockIdx.x * blockDim.x + threadIdx.x;
    if (i < N) g_dinv[i] = rsqrtf((float)g_deg[i] + 1.0f);  // +1 = self loop
}

__global__ void k_norm(const int* __restrict__ row, const int* __restrict__ col, int E) {
    int e = blockIdx.x * blockDim.x + threadIdx.x;
    if (e < E) g_norm[e] = g_dinv[row[e]] * g_dinv[col[e]];
}

// ---------------------------------------------------------------
// GEMM: out[N,64] = act(in)[N,64] @ W[64,64]
// act = identity, or BN(eval)+ReLU fused on the input load (use_bn=1).
// Block: 256 threads, 32 rows per block. W + X tile in smem.
// ---------------------------------------------------------------
#define GEMM_ROWS 32

__global__ __launch_bounds__(256)
void k_gemm(const float* __restrict__ in, const float* __restrict__ W,
            float* __restrict__ out, int N,
            const float* __restrict__ gam, const float* __restrict__ bet,
            const float* __restrict__ mu,  const float* __restrict__ var,
            int use_bn)
{
    __shared__ float Ws[64][64];
    __shared__ float Xs[GEMM_ROWS][64];
    __shared__ float a_s[64], c_s[64];

    int tid = threadIdx.x;

    // load W
    #pragma unroll
    for (int i = tid; i < 64 * 64; i += 256)
        Ws[i >> 6][i & 63] = W[i];

    if (use_bn) {
        for (int k = tid; k < 64; k += 256) {
            float a = gam[k] * rsqrtf(var[k] + EPS);
            a_s[k] = a;
            c_s[k] = bet[k] - mu[k] * a;
        }
    }
    __syncthreads();

    int row0 = blockIdx.x * GEMM_ROWS;

    // load input tile (apply BN+ReLU if requested)
    for (int i = tid; i < GEMM_ROWS * 64; i += 256) {
        int r = i >> 6, k = i & 63;
        int gr = row0 + r;
        float x = (gr < N) ? in[(size_t)gr * 64 + k] : 0.0f;
        if (use_bn) x = fmaxf(fmaf(x, a_s[k], c_s[k]), 0.0f);
        Xs[r][k] = x;
    }
    __syncthreads();

    int c  = tid & 63;       // output column; warp covers 32 contiguous c -> conflict-free
    int ry = tid >> 6;       // 0..3

    for (int r = ry; r < GEMM_ROWS; r += 4) {
        float acc = 0.0f;
        #pragma unroll
        for (int k = 0; k < 64; k++)
            acc = fmaf(Xs[r][k], Ws[k][c], acc);
        int gr = row0 + r;
        if (gr < N) out[(size_t)gr * 64 + c] = acc;
    }
}

// ---------------------------------------------------------------
// agg_init: out[i,:] = h[i,:]*dinv[i]^2 + b   (self-loop term + bias)
// one thread per float4 (16 threads / node)
// ---------------------------------------------------------------
__global__ __launch_bounds__(256)
void k_agg_init(const float* __restrict__ h, const float* __restrict__ b,
                float* __restrict__ out, int N)
{
    int idx = blockIdx.x * blockDim.x + threadIdx.x;
    if (idx >= N * 16) return;
    int i = idx >> 4, k = idx & 15;
    float di = g_dinv[i];
    float s  = di * di;
    float4 hv = reinterpret_cast<const float4*>(h)[(size_t)i * 16 + k];
    float4 bv = reinterpret_cast<const float4*>(b)[k];
    float4 o;
    o.x = fmaf(hv.x, s, bv.x);
    o.y = fmaf(hv.y, s, bv.y);
    o.z = fmaf(hv.z, s, bv.z);
    o.w = fmaf(hv.w, s, bv.w);
    reinterpret_cast<float4*>(out)[(size_t)i * 16 + k] = o;
}

// ---------------------------------------------------------------
// edge scatter: out[row[e],:] += h[col[e],:] * norm[e]
// 16 threads per edge, each owns one float4; vectorized reduction (REDG.v4)
// ---------------------------------------------------------------
__global__ __launch_bounds__(256)
void k_agg_edges(const int* __restrict__ row, const int* __restrict__ col,
                 const float* __restrict__ h, float* __restrict__ out, int E)
{
    int idx = blockIdx.x * blockDim.x + threadIdx.x;
    if (idx >= E * 16) return;
    int e = idx >> 4, k = idx & 15;
    int r = row[e];
    int c = col[e];
    float nrm = g_norm[e];
    float4 hv = reinterpret_cast<const float4*>(h)[(size_t)c * 16 + k];
    float* p = out + ((size_t)r << 6) + (k << 2);
    asm volatile("red.global.add.v4.f32 [%0], {%1,%2,%3,%4};"
                 :: "l"(p), "f"(hv.x * nrm), "f"(hv.y * nrm),
                    "f"(hv.z * nrm), "f"(hv.w * nrm)
                 : "memory");
}

// ---------------------------------------------------------------
// standalone BN(eval)+ReLU: produces the embeddings output
// ---------------------------------------------------------------
__global__ __launch_bounds__(256)
void k_bnrelu(const float* __restrict__ in, float* __restrict__ out, int N,
              const float* __restrict__ gam, const float* __restrict__ bet,
              const float* __restrict__ mu,  const float* __restrict__ var)
{
    int idx = blockIdx.x * blockDim.x + threadIdx.x;
    if (idx >= N * 16) return;
    int k4 = (idx & 15) << 2;   // channel base
    float4 x = reinterpret_cast<const float4*>(in)[idx];
    float4 o;
    {
        float a = gam[k4+0] * rsqrtf(var[k4+0] + EPS);
        o.x = fmaxf(fmaf(x.x, a, bet[k4+0] - mu[k4+0] * a), 0.0f);
    }
    {
        float a = gam[k4+1] * rsqrtf(var[k4+1] + EPS);
        o.y = fmaxf(fmaf(x.y, a, bet[k4+1] - mu[k4+1] * a), 0.0f);
    }
    {
        float a = gam[k4+2] * rsqrtf(var[k4+2] + EPS);
        o.z = fmaxf(fmaf(x.z, a, bet[k4+2] - mu[k4+2] * a), 0.0f);
    }
    {
        float a = gam[k4+3] * rsqrtf(var[k4+3] + EPS);
        o.w = fmaxf(fmaf(x.w, a, bet[k4+3] - mu[k4+3] * a), 0.0f);
    }
    reinterpret_cast<float4*>(out)[idx] = o;
}

// ---------------------------------------------------------------
// launch
// ---------------------------------------------------------------
extern "C" void kernel_launch(void* const* d_in, const int* in_sizes, int n_in,
                              void* d_out, int out_size)
{
    const float* x   = (const float*)d_in[0];
    const int*   ei  = (const int*)  d_in[1];
    const float* W1  = (const float*)d_in[2];
    const float* b1  = (const float*)d_in[3];
    const float* g1  = (const float*)d_in[4];
    const float* be1 = (const float*)d_in[5];
    const float* m1  = (const float*)d_in[6];
    const float* v1  = (const float*)d_in[7];
    const float* W2  = (const float*)d_in[8];
    const float* b2  = (const float*)d_in[9];
    const float* g2  = (const float*)d_in[10];
    const float* be2 = (const float*)d_in[11];
    const float* m2  = (const float*)d_in[12];
    const float* v2  = (const float*)d_in[13];
    const float* W3  = (const float*)d_in[14];
    const float* b3  = (const float*)d_in[15];

    int N = in_sizes[0] / 64;
    int E = in_sizes[1] / 2;

    const int* row = ei;
    const int* col = ei + E;

    float* out  = (float*)d_out;
    float* emb  = out;                       // global_embeddings  [N,64]
    float* pred = out + (size_t)N * 64;      // hc_predictions     [N,64]

    float *p_h = nullptr, *p_agg = nullptr;
    cudaGetSymbolAddress((void**)&p_h,   g_h);
    cudaGetSymbolAddress((void**)&p_agg, g_agg);

    const int T = 256;
    int gN   = (N + T - 1) / T;
    int gE   = (E + T - 1) / T;
    int gN16 = (N * 16 + T - 1) / T;
    int gE16 = (E * 16 + T - 1) / T;
    int gG   = (N + GEMM_ROWS - 1) / GEMM_ROWS;

    // normalization (computed once, reused by all three convs)
    k_zero_deg<<<gN, T>>>(N);
    k_count   <<<gE, T>>>(row, E);
    k_dinv    <<<gN, T>>>(N);
    k_norm    <<<gE, T>>>(row, col, E);

    // layer 1: conv(x, W1) + b1
    k_gemm     <<<gG,   T>>>(x, W1, p_h, N, nullptr, nullptr, nullptr, nullptr, 0);
    k_agg_init <<<gN16, T>>>(p_h, b1, p_agg, N);
    k_agg_edges<<<gE16, T>>>(row, col, p_h, p_agg, E);

    // layer 2: conv(relu(bn1(h)), W2) + b2   (BN+ReLU fused into GEMM input)
    k_gemm     <<<gG,   T>>>(p_agg, W2, p_h, N, g1, be1, m1, v1, 1);
    k_agg_init <<<gN16, T>>>(p_h, b2, p_agg, N);
    k_agg_edges<<<gE16, T>>>(row, col, p_h, p_agg, E);

    // embeddings = relu(bn2(h))  -> first half of d_out
    k_bnrelu<<<gN16, T>>>(p_agg, emb, N, g2, be2, m2, v2);

    // layer 3: conv(emb, W3) + b3 -> second half of d_out
    k_gemm     <<<gG,   T>>>(emb, W3, p_h, N, nullptr, nullptr, nullptr, nullptr, 0);
    k_agg_init <<<gN16, T>>>(p_h, b3, pred, N);
    k_agg_edges<<<gE16, T>>>(row, col, p_h, pred, E);
}

// round 2
// speedup vs baseline: 1.5182x; 1.5182x over previous
#include <cuda_runtime.h>
#include <math.h>

#define NMAX 100000
#define EMAX 1600000
#define EPS 1e-5f
#define SCAN_BLK 1024
#define MAX_BLKS 128   // ceil(100000/1024)=98 <= 128

// ---- device scratch (no allocations allowed) ----
__device__ int   g_deg [NMAX];
__device__ int   g_off [NMAX + 1];
__device__ int   g_cur [NMAX];
__device__ int   g_bsum[MAX_BLKS];
__device__ float g_dinv[NMAX];
__device__ int2  g_csr [EMAX];                  // packed (col, norm bits)
__device__ float g_h   [(size_t)NMAX * 64];
__device__ float g_agg [(size_t)NMAX * 64];

// ------------------- CSR build -------------------
__global__ void k_zero_deg(int N) {
    int i = blockIdx.x * blockDim.x + threadIdx.x;
    if (i < N) g_deg[i] = 0;
}

__global__ void k_count(const int* __restrict__ row, int E) {
    int e = blockIdx.x * blockDim.x + threadIdx.x;
    if (e < E) atomicAdd(&g_deg[row[e]], 1);
}

__global__ void k_dinv(int N) {
    int i = blockIdx.x * blockDim.x + threadIdx.x;
    if (i < N) g_dinv[i] = rsqrtf((float)g_deg[i] + 1.0f);  // +1 = self loop
}

// block-level exclusive scan of g_deg -> g_off (partial), block sums -> g_bsum
__global__ __launch_bounds__(SCAN_BLK)
void k_scan1(int N) {
    __shared__ int s[SCAN_BLK];
    int i = blockIdx.x * SCAN_BLK + threadIdx.x;
    int v = (i < N) ? g_deg[i] : 0;
    s[threadIdx.x] = v;
    __syncthreads();
    #pragma unroll
    for (int d = 1; d < SCAN_BLK; d <<= 1) {
        int t = (threadIdx.x >= d) ? s[threadIdx.x - d] : 0;
        __syncthreads();
        s[threadIdx.x] += t;
        __syncthreads();
    }
    if (i < N) g_off[i] = s[threadIdx.x] - v;          // exclusive within block
    if (threadIdx.x == SCAN_BLK - 1) g_bsum[blockIdx.x] = s[SCAN_BLK - 1];
}

// exclusive scan of block sums (single block)
__global__ __launch_bounds__(MAX_BLKS)
void k_scan2(int nb) {
    __shared__ int s[MAX_BLKS];
    int v = (threadIdx.x < nb) ? g_bsum[threadIdx.x] : 0;
    s[threadIdx.x] = v;
    __syncthreads();
    #pragma unroll
    for (int d = 1; d < MAX_BLKS; d <<= 1) {
        int t = (threadIdx.x >= d) ? s[threadIdx.x - d] : 0;
        __syncthreads();
        s[threadIdx.x] += t;
        __syncthreads();
    }
    if (threadIdx.x < nb) g_bsum[threadIdx.x] = s[threadIdx.x] - v;
}

// add block prefixes; init cursors; set sentinel
__global__ void k_scan3(int N, int E) {
    int i = blockIdx.x * blockDim.x + threadIdx.x;
    if (i < N) {
        int o = g_off[i] + g_bsum[i >> 10];
        g_off[i] = o;
        g_cur[i] = o;
    }
    if (i == 0) g_off[N] = E;
}

// scatter edges into CSR slots, packing (col, norm)
__global__ void k_build(const int* __restrict__ row, const int* __restrict__ col, int E) {
    int e = blockIdx.x * blockDim.x + threadIdx.x;
    if (e >= E) return;
    int r = row[e], c = col[e];
    int pos = atomicAdd(&g_cur[r], 1);
    int2 cn;
    cn.x = c;
    cn.y = __float_as_int(g_dinv[r] * g_dinv[c]);
    g_csr[pos] = cn;
}

// ------------------- GEMM: out = in @ W -------------------
#define GEMM_ROWS 32

__global__ __launch_bounds__(256)
void k_gemm(const float* __restrict__ in, const float* __restrict__ W,
            float* __restrict__ out, int N)
{
    __shared__ float Ws[64][64];
    __shared__ float Xs[GEMM_ROWS][64];

    int tid = threadIdx.x;
    #pragma unroll
    for (int i = tid; i < 64 * 64; i += 256)
        Ws[i >> 6][i & 63] = W[i];

    int row0 = blockIdx.x * GEMM_ROWS;
    for (int i = tid; i < GEMM_ROWS * 64; i += 256) {
        int r = i >> 6, k = i & 63;
        int gr = row0 + r;
        Xs[r][k] = (gr < N) ? in[(size_t)gr * 64 + k] : 0.0f;
    }
    __syncthreads();

    int c  = tid & 63;
    int ry = tid >> 6;
    for (int r = ry; r < GEMM_ROWS; r += 4) {
        float acc = 0.0f;
        #pragma unroll
        for (int k = 0; k < 64; k++)
            acc = fmaf(Xs[r][k], Ws[k][c], acc);
        int gr = row0 + r;
        if (gr < N) out[(size_t)gr * 64 + c] = acc;
    }
}

// ------------------- pull aggregation -------------------
// out[i,:] = act( bias + h[i,:]*dinv[i]^2 + sum_p h[csr_col[p],:]*csr_nrm[p] )
// act = identity (use_bn=0) or relu(bn(.)) (use_bn=1), per-channel affine precomputed.
// 16 threads/node, one float4 lane each. All 16 read the same csr entry (L1 bcast).
__global__ __launch_bounds__(256)
void k_pull(const float* __restrict__ h, const float* __restrict__ bias,
            float* __restrict__ out, int N,
            const float* __restrict__ gam, const float* __restrict__ bet,
            const float* __restrict__ mu,  const float* __restrict__ var,
            int use_bn)
{
    int idx = blockIdx.x * blockDim.x + threadIdx.x;
    if (idx >= N * 16) return;
    int i = idx >> 4, k = idx & 15;

    const float4* h4 = reinterpret_cast<const float4*>(h);

    float4 acc = reinterpret_cast<const float4*>(bias)[k];
    float  di  = g_dinv[i];
    float  s2  = di * di;
    float4 hv  = h4[(size_t)i * 16 + k];
    acc.x = fmaf(hv.x, s2, acc.x);
    acc.y = fmaf(hv.y, s2, acc.y);
    acc.z = fmaf(hv.z, s2, acc.z);
    acc.w = fmaf(hv.w, s2, acc.w);

    int p   = g_off[i];
    int end = g_off[i + 1];

    // unroll-by-2 with prefetch of the edge record
    for (; p + 2 <= end; p += 2) {
        int2 cn0 = g_csr[p];
        int2 cn1 = g_csr[p + 1];
        float n0 = __int_as_float(cn0.y);
        float n1 = __int_as_float(cn1.y);
        float4 v0 = h4[(size_t)cn0.x * 16 + k];
        float4 v1 = h4[(size_t)cn1.x * 16 + k];
        acc.x = fmaf(v0.x, n0, acc.x);
        acc.y = fmaf(v0.y, n0, acc.y);
        acc.z = fmaf(v0.z, n0, acc.z);
        acc.w = fmaf(v0.w, n0, acc.w);
        acc.x = fmaf(v1.x, n1, acc.x);
        acc.y = fmaf(v1.y, n1, acc.y);
        acc.z = fmaf(v1.z, n1, acc.z);
        acc.w = fmaf(v1.w, n1, acc.w);
    }
    if (p < end) {
        int2 cn = g_csr[p];
        float nrm = __int_as_float(cn.y);
        float4 v = h4[(size_t)cn.x * 16 + k];
        acc.x = fmaf(v.x, nrm, acc.x);
        acc.y = fmaf(v.y, nrm, acc.y);
        acc.z = fmaf(v.z, nrm, acc.z);
        acc.w = fmaf(v.w, nrm, acc.w);
    }

    if (use_bn) {
        int k4 = k << 2;
        #pragma unroll
        for (int j = 0; j < 4; j++) {
            float a = gam[k4 + j] * rsqrtf(var[k4 + j] + EPS);
            float c = bet[k4 + j] - mu[k4 + j] * a;
            float* f = (&acc.x) + j;
            *f = fmaxf(fmaf(*f, a, c), 0.0f);
        }
    }

    reinterpret_cast<float4*>(out)[(size_t)i * 16 + k] = acc;
}

// ------------------- launch -------------------
extern "C" void kernel_launch(void* const* d_in, const int* in_sizes, int n_in,
                              void* d_out, int out_size)
{
    const float* x   = (const float*)d_in[0];
    const int*   ei  = (const int*)  d_in[1];
    const float* W1  = (const float*)d_in[2];
    const float* b1  = (const float*)d_in[3];
    const float* g1  = (const float*)d_in[4];
    const float* be1 = (const float*)d_in[5];
    const float* m1  = (const float*)d_in[6];
    const float* v1  = (const float*)d_in[7];
    const float* W2  = (const float*)d_in[8];
    const float* b2  = (const float*)d_in[9];
    const float* g2  = (const float*)d_in[10];
    const float* be2 = (const float*)d_in[11];
    const float* m2  = (const float*)d_in[12];
    const float* v2  = (const float*)d_in[13];
    const float* W3  = (const float*)d_in[14];
    const float* b3  = (const float*)d_in[15];

    int N = in_sizes[0] / 64;
    int E = in_sizes[1] / 2;

    const int* row = ei;
    const int* col = ei + E;

    float* out  = (float*)d_out;
    float* emb  = out;                      // global_embeddings [N,64]
    float* pred = out + (size_t)N * 64;     // hc_predictions    [N,64]

    float *p_h = nullptr, *p_agg = nullptr;
    cudaGetSymbolAddress((void**)&p_h,   g_h);
    cudaGetSymbolAddress((void**)&p_agg, g_agg);

    const int T = 256;
    int gN   = (N + T - 1) / T;
    int gE   = (E + T - 1) / T;
    int gN16 = (N * 16 + T - 1) / T;
    int gG   = (N + GEMM_ROWS - 1) / GEMM_ROWS;
    int nb   = (N + SCAN_BLK - 1) / SCAN_BLK;

    // ---- CSR build (once per launch, reused by all 3 convs) ----
    k_zero_deg<<<gN, T>>>(N);
    k_count   <<<gE, T>>>(row, E);
    k_dinv    <<<gN, T>>>(N);
    k_scan1   <<<nb, SCAN_BLK>>>(N);
    k_scan2   <<<1, MAX_BLKS>>>(nb);
    k_scan3   <<<gN, T>>>(N, E);
    k_build   <<<gE, T>>>(row, col, E);

    // ---- layer 1: h = relu(bn1(conv(x, W1) + b1)) ----
    k_gemm<<<gG,   T>>>(x, W1, p_h, N);
    k_pull<<<gN16, T>>>(p_h, b1, p_agg, N, g1, be1, m1, v1, 1);

    // ---- layer 2: emb = relu(bn2(conv(h, W2) + b2)) -> d_out[0:N*64] ----
    k_gemm<<<gG,   T>>>(p_agg, W2, p_h, N);
    k_pull<<<gN16, T>>>(p_h, b2, emb, N, g2, be2, m2, v2, 1);

    // ---- layer 3: pred = conv(emb, W3) + b3 -> d_out[N*64:] ----
    k_gemm<<<gG,   T>>>(emb, W3, p_h, N);
    k_pull<<<gN16, T>>>(p_h, b3, pred, N, nullptr, nullptr, nullptr, nullptr, 0);
}

// round 3
// speedup vs baseline: 2.0353x; 1.3406x over previous
#include <cuda_runtime.h>
#include <math.h>

#define NMAX 100000
#define EMAX 1600000
#define EPS 1e-5f
#define SCAN_BLK 1024
#define MAX_BLKS 128   // ceil(100000/1024)=98 <= 128

// ---- device scratch (no allocations allowed) ----
__device__ int   g_deg [NMAX];
__device__ int   g_off [NMAX + 1];
__device__ int   g_cur [NMAX];
__device__ int   g_bsum[MAX_BLKS];
__device__ float g_dinv[NMAX];
__device__ int2  g_csr [EMAX];                  // packed (col, norm bits)
__device__ float g_h   [(size_t)NMAX * 64];
__device__ float g_agg [(size_t)NMAX * 64];

// ------------------- CSR build -------------------
__global__ void k_zero_deg(int N) {
    int i = blockIdx.x * blockDim.x + threadIdx.x;
    if (i < N) g_deg[i] = 0;
}

__global__ void k_count(const int* __restrict__ row, int E) {
    int e = blockIdx.x * blockDim.x + threadIdx.x;
    if (e < E) atomicAdd(&g_deg[row[e]], 1);
}

__global__ void k_dinv(int N) {
    int i = blockIdx.x * blockDim.x + threadIdx.x;
    if (i < N) g_dinv[i] = rsqrtf((float)g_deg[i] + 1.0f);  // +1 = self loop
}

__global__ __launch_bounds__(SCAN_BLK)
void k_scan1(int N) {
    __shared__ int s[SCAN_BLK];
    int i = blockIdx.x * SCAN_BLK + threadIdx.x;
    int v = (i < N) ? g_deg[i] : 0;
    s[threadIdx.x] = v;
    __syncthreads();
    #pragma unroll
    for (int d = 1; d < SCAN_BLK; d <<= 1) {
        int t = (threadIdx.x >= d) ? s[threadIdx.x - d] : 0;
        __syncthreads();
        s[threadIdx.x] += t;
        __syncthreads();
    }
    if (i < N) g_off[i] = s[threadIdx.x] - v;
    if (threadIdx.x == SCAN_BLK - 1) g_bsum[blockIdx.x] = s[SCAN_BLK - 1];
}

__global__ __launch_bounds__(MAX_BLKS)
void k_scan2(int nb) {
    __shared__ int s[MAX_BLKS];
    int v = (threadIdx.x < nb) ? g_bsum[threadIdx.x] : 0;
    s[threadIdx.x] = v;
    __syncthreads();
    #pragma unroll
    for (int d = 1; d < MAX_BLKS; d <<= 1) {
        int t = (threadIdx.x >= d) ? s[threadIdx.x - d] : 0;
        __syncthreads();
        s[threadIdx.x] += t;
        __syncthreads();
    }
    if (threadIdx.x < nb) g_bsum[threadIdx.x] = s[threadIdx.x] - v;
}

__global__ void k_scan3(int N, int E) {
    int i = blockIdx.x * blockDim.x + threadIdx.x;
    if (i < N) {
        int o = g_off[i] + g_bsum[i >> 10];
        g_off[i] = o;
        g_cur[i] = o;
    }
    if (i == 0) g_off[N] = E;
}

__global__ void k_build(const int* __restrict__ row, const int* __restrict__ col, int E) {
    int e = blockIdx.x * blockDim.x + threadIdx.x;
    if (e >= E) return;
    int r = row[e], c = col[e];
    int pos = atomicAdd(&g_cur[r], 1);
    int2 cn;
    cn.x = c;
    cn.y = __float_as_int(g_dinv[r] * g_dinv[c]);
    g_csr[pos] = cn;
}

// ------------------- GEMM: out = in @ W -------------------
// 256 threads, 64 rows/block. 4x4 register blocking:
// thread (cg = tid&15 -> 4 cols, rg = tid>>4 -> 4 rows).
#define GEMM_ROWS 64

__global__ __launch_bounds__(256)
void k_gemm(const float* __restrict__ in, const float* __restrict__ W,
            float* __restrict__ out, int N)
{
    __shared__ float Ws[64][64];
    __shared__ float Xs[GEMM_ROWS][64];

    int tid = threadIdx.x;
    int row0 = blockIdx.x * GEMM_ROWS;

    #pragma unroll
    for (int i = tid; i < 64 * 64; i += 256)
        Ws[i >> 6][i & 63] = W[i];

    #pragma unroll
    for (int i = tid; i < GEMM_ROWS * 64 / 4; i += 256) {
        int r = i >> 4, k4 = (i & 15);
        int gr = row0 + r;
        float4 v = (gr < N) ? reinterpret_cast<const float4*>(in)[(size_t)gr * 16 + k4]
                            : make_float4(0.f, 0.f, 0.f, 0.f);
        reinterpret_cast<float4*>(&Xs[r][0])[k4] = v;
    }
    __syncthreads();

    int cg = tid & 15;          // 4 output columns: cg*4 ..
    int rg = tid >> 4;          // 4 rows: rg*4 ..
    int r0 = rg * 4;

    float acc[4][4];
    #pragma unroll
    for (int a = 0; a < 4; a++)
        #pragma unroll
        for (int b = 0; b < 4; b++)
            acc[a][b] = 0.0f;

    #pragma unroll
    for (int k = 0; k < 64; k++) {
        float4 wv = reinterpret_cast<const float4*>(&Ws[k][0])[cg];
        float xv0 = Xs[r0 + 0][k];
        float xv1 = Xs[r0 + 1][k];
        float xv2 = Xs[r0 + 2][k];
        float xv3 = Xs[r0 + 3][k];
        acc[0][0] = fmaf(xv0, wv.x, acc[0][0]);
        acc[0][1] = fmaf(xv0, wv.y, acc[0][1]);
        acc[0][2] = fmaf(xv0, wv.z, acc[0][2]);
        acc[0][3] = fmaf(xv0, wv.w, acc[0][3]);
        acc[1][0] = fmaf(xv1, wv.x, acc[1][0]);
        acc[1][1] = fmaf(xv1, wv.y, acc[1][1]);
        acc[1][2] = fmaf(xv1, wv.z, acc[1][2]);
        acc[1][3] = fmaf(xv1, wv.w, acc[1][3]);
        acc[2][0] = fmaf(xv2, wv.x, acc[2][0]);
        acc[2][1] = fmaf(xv2, wv.y, acc[2][1]);
        acc[2][2] = fmaf(xv2, wv.z, acc[2][2]);
        acc[2][3] = fmaf(xv2, wv.w, acc[2][3]);
        acc[3][0] = fmaf(xv3, wv.x, acc[3][0]);
        acc[3][1] = fmaf(xv3, wv.y, acc[3][1]);
        acc[3][2] = fmaf(xv3, wv.z, acc[3][2]);
        acc[3][3] = fmaf(xv3, wv.w, acc[3][3]);
    }

    #pragma unroll
    for (int a = 0; a < 4; a++) {
        int gr = row0 + r0 + a;
        if (gr < N) {
            float4 o = make_float4(acc[a][0], acc[a][1], acc[a][2], acc[a][3]);
            reinterpret_cast<float4*>(out)[(size_t)gr * 16 + cg] = o;
        }
    }
}

// ------------------- pull aggregation -------------------
// out[i,:] = act( bias + h[i,:]*dinv[i]^2 + sum_p h[csr_col[p],:]*csr_nrm[p] )
// 16 threads/node, one float4 lane each. Chunked warp-cooperative edge loads:
// 16 lanes load 16 consecutive records (coalesced), shfl-broadcast, then 16
// independent gathers fully unrolled (MLP ~16).
__global__ __launch_bounds__(256)
void k_pull(const float* __restrict__ h, const float* __restrict__ bias,
            float* __restrict__ out, int N,
            const float* __restrict__ gam, const float* __restrict__ bet,
            const float* __restrict__ mu,  const float* __restrict__ var,
            int use_bn)
{
    int idx = blockIdx.x * blockDim.x + threadIdx.x;
    if (idx >= N * 16) return;
    int i = idx >> 4, k = idx & 15;

    const float4* h4 = reinterpret_cast<const float4*>(h);
    unsigned mask = 0xFFFFu << (threadIdx.x & 16);   // this 16-lane group

    float4 acc = reinterpret_cast<const float4*>(bias)[k];
    float  di  = g_dinv[i];
    float  s2  = di * di;
    float4 hv  = h4[(size_t)i * 16 + k];
    acc.x = fmaf(hv.x, s2, acc.x);
    acc.y = fmaf(hv.y, s2, acc.y);
    acc.z = fmaf(hv.z, s2, acc.z);
    acc.w = fmaf(hv.w, s2, acc.w);

    int p   = g_off[i];
    int end = g_off[i + 1];

    for (; p < end; p += 16) {
        int m  = end - p;                 // >= 1
        int pk = p + k;
        int2 rec = g_csr[(pk < end) ? pk : p];   // clamped (unused lanes read p)

        int   cj[16];
        float nj[16];
        #pragma unroll
        for (int j = 0; j < 16; j++) {
            cj[j] = __shfl_sync(mask, rec.x, j, 16);
            nj[j] = __int_as_float(__shfl_sync(mask, rec.y, j, 16));
        }

        #pragma unroll
        for (int j = 0; j < 16; j++) {
            if (j < m) {                   // uniform within the 16-lane group
                float4 v = __ldg(&h4[(size_t)cj[j] * 16 + k]);
                acc.x = fmaf(v.x, nj[j], acc.x);
                acc.y = fmaf(v.y, nj[j], acc.y);
                acc.z = fmaf(v.z, nj[j], acc.z);
                acc.w = fmaf(v.w, nj[j], acc.w);
            }
        }
    }

    if (use_bn) {
        int k4 = k << 2;
        #pragma unroll
        for (int j = 0; j < 4; j++) {
            float a = gam[k4 + j] * rsqrtf(var[k4 + j] + EPS);
            float c = bet[k4 + j] - mu[k4 + j] * a;
            float* f = (&acc.x) + j;
            *f = fmaxf(fmaf(*f, a, c), 0.0f);
        }
    }

    reinterpret_cast<float4*>(out)[(size_t)i * 16 + k] = acc;
}

// ------------------- launch -------------------
extern "C" void kernel_launch(void* const* d_in, const int* in_sizes, int n_in,
                              void* d_out, int out_size)
{
    const float* x   = (const float*)d_in[0];
    const int*   ei  = (const int*)  d_in[1];
    const float* W1  = (const float*)d_in[2];
    const float* b1  = (const float*)d_in[3];
    const float* g1  = (const float*)d_in[4];
    const float* be1 = (const float*)d_in[5];
    const float* m1  = (const float*)d_in[6];
    const float* v1  = (const float*)d_in[7];
    const float* W2  = (const float*)d_in[8];
    const float* b2  = (const float*)d_in[9];
    const float* g2  = (const float*)d_in[10];
    const float* be2 = (const float*)d_in[11];
    const float* m2  = (const float*)d_in[12];
    const float* v2  = (const float*)d_in[13];
    const float* W3  = (const float*)d_in[14];
    const float* b3  = (const float*)d_in[15];

    int N = in_sizes[0] / 64;
    int E = in_sizes[1] / 2;

    const int* row = ei;
    const int* col = ei + E;

    float* out  = (float*)d_out;
    float* emb  = out;                      // global_embeddings [N,64]
    float* pred = out + (size_t)N * 64;     // hc_predictions    [N,64]

    float *p_h = nullptr, *p_agg = nullptr;
    cudaGetSymbolAddress((void**)&p_h,   g_h);
    cudaGetSymbolAddress((void**)&p_agg, g_agg);

    const int T = 256;
    int gN   = (N + T - 1) / T;
    int gE   = (E + T - 1) / T;
    int gN16 = (N * 16 + T - 1) / T;
    int gG   = (N + GEMM_ROWS - 1) / GEMM_ROWS;
    int nb   = (N + SCAN_BLK - 1) / SCAN_BLK;

    // ---- CSR build (once per launch, reused by all 3 convs) ----
    k_zero_deg<<<gN, T>>>(N);
    k_count   <<<gE, T>>>(row, E);
    k_dinv    <<<gN, T>>>(N);
    k_scan1   <<<nb, SCAN_BLK>>>(N);
    k_scan2   <<<1, MAX_BLKS>>>(nb);
    k_scan3   <<<gN, T>>>(N, E);
    k_build   <<<gE, T>>>(row, col, E);

    // ---- layer 1: h = relu(bn1(conv(x, W1) + b1)) ----
    k_gemm<<<gG,   T>>>(x, W1, p_h, N);
    k_pull<<<gN16, T>>>(p_h, b1, p_agg, N, g1, be1, m1, v1, 1);

    // ---- layer 2: emb = relu(bn2(conv(h, W2) + b2)) -> d_out[0:N*64] ----
    k_gemm<<<gG,   T>>>(p_agg, W2, p_h, N);
    k_pull<<<gN16, T>>>(p_h, b2, emb, N, g2, be2, m2, v2, 1);

    // ---- layer 3: pred = conv(emb, W3) + b3 -> d_out[N*64:] ----
    k_gemm<<<gG,   T>>>(emb, W3, p_h, N);
    k_pull<<<gN16, T>>>(p_h, b3, pred, N, nullptr, nullptr, nullptr, nullptr, 0);
}

// round 4
// speedup vs baseline: 2.2027x; 1.0822x over previous
#include <cuda_runtime.h>
#include <cuda_fp16.h>
#include <math.h>

#define NMAX 100000
#define EMAX 1600000
#define EPS 1e-5f
#define SCAN_BLK 1024
#define MAX_BLKS 128   // ceil(100000/1024)=98 <= 128

// ---- device scratch (no allocations allowed) ----
__device__ int    g_deg [NMAX];
__device__ int    g_off [NMAX + 1];
__device__ int    g_cur [NMAX];
__device__ int    g_bsum[MAX_BLKS];
__device__ float  g_dinv[NMAX];
__device__ int    g_csr [EMAX];                    // col index only
__device__ __half g_h   [(size_t)NMAX * 64];       // dinv-prescaled GEMM output (fp16)
__device__ float  g_agg [(size_t)NMAX * 64];

// ------------------- CSR build -------------------
__global__ void k_zero_deg(int N) {
    int i = blockIdx.x * blockDim.x + threadIdx.x;
    if (i < N) g_deg[i] = 0;
}

__global__ void k_count(const int* __restrict__ row, int E) {
    int e = blockIdx.x * blockDim.x + threadIdx.x;
    if (e < E) atomicAdd(&g_deg[row[e]], 1);
}

// scan of deg -> partial g_off; also dinv = rsqrt(deg+1)
__global__ __launch_bounds__(SCAN_BLK)
void k_scan1(int N) {
    __shared__ int s[SCAN_BLK];
    int i = blockIdx.x * SCAN_BLK + threadIdx.x;
    int v = (i < N) ? g_deg[i] : 0;
    if (i < N) g_dinv[i] = rsqrtf((float)v + 1.0f);   // +1 = self loop
    s[threadIdx.x] = v;
    __syncthreads();
    #pragma unroll
    for (int d = 1; d < SCAN_BLK; d <<= 1) {
        int t = (threadIdx.x >= d) ? s[threadIdx.x - d] : 0;
        __syncthreads();
        s[threadIdx.x] += t;
        __syncthreads();
    }
    if (i < N) g_off[i] = s[threadIdx.x] - v;
    if (threadIdx.x == SCAN_BLK - 1) g_bsum[blockIdx.x] = s[SCAN_BLK - 1];
}

__global__ __launch_bounds__(MAX_BLKS)
void k_scan2(int nb) {
    __shared__ int s[MAX_BLKS];
    int v = (threadIdx.x < nb) ? g_bsum[threadIdx.x] : 0;
    s[threadIdx.x] = v;
    __syncthreads();
    #pragma unroll
    for (int d = 1; d < MAX_BLKS; d <<= 1) {
        int t = (threadIdx.x >= d) ? s[threadIdx.x - d] : 0;
        __syncthreads();
        s[threadIdx.x] += t;
        __syncthreads();
    }
    if (threadIdx.x < nb) g_bsum[threadIdx.x] = s[threadIdx.x] - v;
}

__global__ void k_scan3(int N, int E) {
    int i = blockIdx.x * blockDim.x + threadIdx.x;
    if (i < N) {
        int o = g_off[i] + g_bsum[i >> 10];
        g_off[i] = o;
        g_cur[i] = o;
    }
    if (i == 0) g_off[N] = E;
}

__global__ void k_build(const int* __restrict__ row, const int* __restrict__ col, int E) {
    int e = blockIdx.x * blockDim.x + threadIdx.x;
    if (e >= E) return;
    int pos = atomicAdd(&g_cur[row[e]], 1);
    g_csr[pos] = col[e];
}

// ------------------- GEMM: hs = (in @ W) * dinv[row], fp16 out -------------------
// 256 threads, 64 rows/block, 4x4 register blocking.
#define GEMM_ROWS 64

__global__ __launch_bounds__(256)
void k_gemm(const float* __restrict__ in, const float* __restrict__ W,
            __half* __restrict__ out, int N)
{
    __shared__ float Ws[64][64];
    __shared__ float Xs[GEMM_ROWS][64];

    int tid = threadIdx.x;
    int row0 = blockIdx.x * GEMM_ROWS;

    #pragma unroll
    for (int i = tid; i < 64 * 64; i += 256)
        Ws[i >> 6][i & 63] = W[i];

    #pragma unroll
    for (int i = tid; i < GEMM_ROWS * 64 / 4; i += 256) {
        int r = i >> 4, k4 = (i & 15);
        int gr = row0 + r;
        float4 v = (gr < N) ? reinterpret_cast<const float4*>(in)[(size_t)gr * 16 + k4]
                            : make_float4(0.f, 0.f, 0.f, 0.f);
        reinterpret_cast<float4*>(&Xs[r][0])[k4] = v;
    }
    __syncthreads();

    int cg = tid & 15;          // 4 output channels: cg*4..
    int rg = tid >> 4;
    int r0 = rg * 4;

    float acc[4][4];
    #pragma unroll
    for (int a = 0; a < 4; a++)
        #pragma unroll
        for (int b = 0; b < 4; b++)
            acc[a][b] = 0.0f;

    #pragma unroll
    for (int k = 0; k < 64; k++) {
        float4 wv = reinterpret_cast<const float4*>(&Ws[k][0])[cg];
        float xv0 = Xs[r0 + 0][k];
        float xv1 = Xs[r0 + 1][k];
        float xv2 = Xs[r0 + 2][k];
        float xv3 = Xs[r0 + 3][k];
        acc[0][0] = fmaf(xv0, wv.x, acc[0][0]);
        acc[0][1] = fmaf(xv0, wv.y, acc[0][1]);
        acc[0][2] = fmaf(xv0, wv.z, acc[0][2]);
        acc[0][3] = fmaf(xv0, wv.w, acc[0][3]);
        acc[1][0] = fmaf(xv1, wv.x, acc[1][0]);
        acc[1][1] = fmaf(xv1, wv.y, acc[1][1]);
        acc[1][2] = fmaf(xv1, wv.z, acc[1][2]);
        acc[1][3] = fmaf(xv1, wv.w, acc[1][3]);
        acc[2][0] = fmaf(xv2, wv.x, acc[2][0]);
        acc[2][1] = fmaf(xv2, wv.y, acc[2][1]);
        acc[2][2] = fmaf(xv2, wv.z, acc[2][2]);
        acc[2][3] = fmaf(xv2, wv.w, acc[2][3]);
        acc[3][0] = fmaf(xv3, wv.x, acc[3][0]);
        acc[3][1] = fmaf(xv3, wv.y, acc[3][1]);
        acc[3][2] = fmaf(xv3, wv.z, acc[3][2]);
        acc[3][3] = fmaf(xv3, wv.w, acc[3][3]);
    }

    #pragma unroll
    for (int a = 0; a < 4; a++) {
        int gr = row0 + r0 + a;
        if (gr < N) {
            float di = g_dinv[gr];
            __half2 p0 = __floats2half2_rn(acc[a][0] * di, acc[a][1] * di);
            __half2 p1 = __floats2half2_rn(acc[a][2] * di, acc[a][3] * di);
            uint2 st;
            st.x = *reinterpret_cast<unsigned*>(&p0);
            st.y = *reinterpret_cast<unsigned*>(&p1);
            // row = 64 halfs = 128 B = 16 uint2
            reinterpret_cast<uint2*>(out)[(size_t)gr * 16 + cg] = st;
        }
    }
}

// ------------------- pull aggregation (fp16 gathers, fp32 accumulate) ----------
// out[i,:] = act( bias + dinv_i * ( hs[i,:] + sum_p hs[csr[p],:] ) )
// 16 threads/node, 4 channels (8 B) per lane. Chunked cooperative edge loads:
// 16 lanes load 16 consecutive cols (64 B coalesced), shfl-broadcast, then 16
// independent 8 B gathers fully unrolled (MLP ~16).
__global__ __launch_bounds__(256)
void k_pull(const __half* __restrict__ h, const float* __restrict__ bias,
            float* __restrict__ out, int N,
            const float* __restrict__ gam, const float* __restrict__ bet,
            const float* __restrict__ mu,  const float* __restrict__ var,
            int use_bn)
{
    int idx = blockIdx.x * blockDim.x + threadIdx.x;
    if (idx >= N * 16) return;
    int i = idx >> 4, k = idx & 15;

    const uint2* h2 = reinterpret_cast<const uint2*>(h);   // 16 uint2 per row
    unsigned mask = 0xFFFFu << (threadIdx.x & 16);

    float4 acc;
    {   // self term
        uint2 sv = __ldg(&h2[(size_t)i * 16 + k]);
        float2 f0 = __half22float2(*reinterpret_cast<__half2*>(&sv.x));
        float2 f1 = __half22float2(*reinterpret_cast<__half2*>(&sv.y));
        acc.x = f0.x; acc.y = f0.y; acc.z = f1.x; acc.w = f1.y;
    }

    int p   = g_off[i];
    int end = g_off[i + 1];

    for (; p < end; p += 16) {
        int m  = end - p;                      // >= 1
        int pk = p + k;
        int cidx = g_csr[(pk < end) ? pk : p]; // clamped coalesced load

        int cj[16];
        #pragma unroll
        for (int j = 0; j < 16; j++)
            cj[j] = __shfl_sync(mask, cidx, j, 16);

        #pragma unroll
        for (int j = 0; j < 16; j++) {
            if (j < m) {                       // uniform within 16-lane group
                uint2 v = __ldg(&h2[(size_t)cj[j] * 16 + k]);
                float2 f0 = __half22float2(*reinterpret_cast<__half2*>(&v.x));
                float2 f1 = __half22float2(*reinterpret_cast<__half2*>(&v.y));
                acc.x += f0.x; acc.y += f0.y; acc.z += f1.x; acc.w += f1.y;
            }
        }
    }

    float di = g_dinv[i];
    float4 bv = reinterpret_cast<const float4*>(bias)[k];
    acc.x = fmaf(acc.x, di, bv.x);
    acc.y = fmaf(acc.y, di, bv.y);
    acc.z = fmaf(acc.z, di, bv.z);
    acc.w = fmaf(acc.w, di, bv.w);

    if (use_bn) {
        int k4 = k << 2;
        #pragma unroll
        for (int j = 0; j < 4; j++) {
            float a = gam[k4 + j] * rsqrtf(var[k4 + j] + EPS);
            float c = bet[k4 + j] - mu[k4 + j] * a;
            float* f = (&acc.x) + j;
            *f = fmaxf(fmaf(*f, a, c), 0.0f);
        }
    }

    reinterpret_cast<float4*>(out)[(size_t)i * 16 + k] = acc;
}

// ------------------- launch -------------------
extern "C" void kernel_launch(void* const* d_in, const int* in_sizes, int n_in,
                              void* d_out, int out_size)
{
    const float* x   = (const float*)d_in[0];
    const int*   ei  = (const int*)  d_in[1];
    const float* W1  = (const float*)d_in[2];
    const float* b1  = (const float*)d_in[3];
    const float* g1  = (const float*)d_in[4];
    const float* be1 = (const float*)d_in[5];
    const float* m1  = (const float*)d_in[6];
    const float* v1  = (const float*)d_in[7];
    const float* W2  = (const float*)d_in[8];
    const float* b2  = (const float*)d_in[9];
    const float* g2  = (const float*)d_in[10];
    const float* be2 = (const float*)d_in[11];
    const float* m2  = (const float*)d_in[12];
    const float* v2  = (const float*)d_in[13];
    const float* W3  = (const float*)d_in[14];
    const float* b3  = (const float*)d_in[15];

    int N = in_sizes[0] / 64;
    int E = in_sizes[1] / 2;

    const int* row = ei;
    const int* col = ei + E;

    float* out  = (float*)d_out;
    float* emb  = out;                      // global_embeddings [N,64]
    float* pred = out + (size_t)N * 64;     // hc_predictions    [N,64]

    __half* p_h = nullptr;
    float*  p_agg = nullptr;
    cudaGetSymbolAddress((void**)&p_h,   g_h);
    cudaGetSymbolAddress((void**)&p_agg, g_agg);

    const int T = 256;
    int gN   = (N + T - 1) / T;
    int gE   = (E + T - 1) / T;
    int gN16 = (N * 16 + T - 1) / T;
    int gG   = (N + GEMM_ROWS - 1) / GEMM_ROWS;
    int nb   = (N + SCAN_BLK - 1) / SCAN_BLK;

    // ---- CSR build (once per launch, reused by all 3 convs) ----
    k_zero_deg<<<gN, T>>>(N);
    k_count   <<<gE, T>>>(row, E);
    k_scan1   <<<nb, SCAN_BLK>>>(N);        // also computes dinv
    k_scan2   <<<1, MAX_BLKS>>>(nb);
    k_scan3   <<<gN, T>>>(N, E);
    k_build   <<<gE, T>>>(row, col, E);

    // ---- layer 1: h = relu(bn1(conv(x, W1) + b1)) ----
    k_gemm<<<gG,   T>>>(x, W1, p_h, N);
    k_pull<<<gN16, T>>>(p_h, b1, p_agg, N, g1, be1, m1, v1, 1);

    // ---- layer 2: emb = relu(bn2(conv(h, W2) + b2)) -> d_out[0:N*64] ----
    k_gemm<<<gG,   T>>>(p_agg, W2, p_h, N);
    k_pull<<<gN16, T>>>(p_h, b2, emb, N, g2, be2, m2, v2, 1);

    // ---- layer 3: pred = conv(emb, W3) + b3 -> d_out[N*64:] ----
    k_gemm<<<gG,   T>>>(emb, W3, p_h, N);
    k_pull<<<gN16, T>>>(p_h, b3, pred, N, nullptr, nullptr, nullptr, nullptr, 0);
}